// round 1
// baseline (speedup 1.0000x reference)
#include <cuda_runtime.h>
#include <cstdint>

// Problem dims (fixed): B=4, T=4096, D_IN=1024, H=16, D=64
// GEMM view: M = B*T = 16384, K = 1024, N = H*D*2 = 2048
#define TB 4
#define TT 4096
#define TDIN 1024
#define TH 16
#define TD 64

// ---------------- scratch (static device arrays; no runtime alloc) ----------
__device__ float g_Xc[16384ull * 1024];      // tf32-rounded X          (64 MB)
__device__ float g_Wc[1024ull * 2048];       // tf32-rounded W          ( 8 MB)
__device__ float g_V [64ull * 4096 * 64];    // v[b*16+h][t][d]         (64 MB)
__device__ float g_S [64ull * 4096];         // s[b*16+h][t]            ( 1 MB)
__device__ float g_Ha[64ull * 4096 * 64];    // (a/c)[b*16+h][t][d]     (64 MB)

// ---------------- kernel 0: round inputs to tf32 (RNA) ----------------------
__global__ void cvt_tf32_kernel(const float4* __restrict__ in, int n4, int which)
{
    int i = blockIdx.x * blockDim.x + threadIdx.x;
    if (i >= n4) return;
    float4 v = in[i];
    uint32_t r;
    asm("cvt.rna.tf32.f32 %0, %1;" : "=r"(r) : "f"(v.x)); v.x = __uint_as_float(r);
    asm("cvt.rna.tf32.f32 %0, %1;" : "=r"(r) : "f"(v.y)); v.y = __uint_as_float(r);
    asm("cvt.rna.tf32.f32 %0, %1;" : "=r"(r) : "f"(v.z)); v.z = __uint_as_float(r);
    asm("cvt.rna.tf32.f32 %0, %1;" : "=r"(r) : "f"(v.w)); v.w = __uint_as_float(r);
    float4* out = which ? (float4*)g_Wc : (float4*)g_Xc;
    out[i] = v;
}

// ---------------- kernel 1: tf32 GEMM + relu + q-dot + v store --------------
// Block tile 128(M) x 128(N), BK=32, 256 threads (2x4 warps, warp = 64x32).
// BN=128 == exactly one head (h*128 .. h*128+127), so the epilogue fuses
// s[b,h,t] = sum_d q[h,d]*relu(k) and v[b,h,t,d] = relu(v) per block.
// Shared memory (dynamic, 67584 B):
//   A stages: 2 x [128][32] f32 (XOR-swizzled float4s for ldmatrix)
//   B stages: 2 x [32][136] f32 (row = k, 128 n + 8 pad for conflict-free LDS)
__global__ __launch_bounds__(256, 2)
void gemm_epilogue_kernel(const float* __restrict__ Qk)
{
    extern __shared__ float smem[];
    const int h   = blockIdx.x;          // 0..15
    const int mt  = blockIdx.y;          // 0..127
    const int m0  = mt << 7;
    const int tid = threadIdx.x;
    const int lane = tid & 31, warp = tid >> 5;
    const int wm  = (warp >> 2) << 6;    // 0 / 64   (M offset)
    const int wnf = (warp & 3) << 5;     // 0/32/64/96 (N float offset)

    const float* Ag = g_Xc + (size_t)m0 * TDIN;
    const float* Bg = g_Wc + (h << 7);

    // gmem->smem copy plan (4 x 16B per thread per operand)
    int aoff[4], boff[4], agoff[4], bgoff[4];
#pragma unroll
    for (int i = 0; i < 4; i++) {
        int id = tid + i * 256;
        int ar = id >> 3, ac4 = id & 7;                    // A: 128 rows x 8 float4
        aoff[i]  = ar * 32 + ((ac4 ^ (ar & 7)) << 2);      // XOR swizzle
        agoff[i] = ar * TDIN + (ac4 << 2);
        int br = id >> 5, bc4 = id & 31;                   // B: 32 rows x 32 float4
        boff[i]  = 8192 + br * 136 + (bc4 << 2);           // B region starts at float 8192
        bgoff[i] = br * 2048 + (bc4 << 2);
    }
    uint32_t smemu = (uint32_t)__cvta_generic_to_shared(smem);

    // prologue: stage 0, k0 = 0
#pragma unroll
    for (int i = 0; i < 4; i++) {
        asm volatile("cp.async.cg.shared.global [%0], [%1], 16;"
                     :: "r"(smemu + 4u * aoff[i]), "l"(Ag + agoff[i]));
        asm volatile("cp.async.cg.shared.global [%0], [%1], 16;"
                     :: "r"(smemu + 4u * boff[i]), "l"(Bg + bgoff[i]));
    }
    asm volatile("cp.async.commit_group;" ::: "memory");

    float acc[4][4][4];
#pragma unroll
    for (int i0 = 0; i0 < 4; i0++)
#pragma unroll
        for (int i1 = 0; i1 < 4; i1++)
#pragma unroll
            for (int i2 = 0; i2 < 4; i2++) acc[i0][i1][i2] = 0.f;

    // fragment addressing constants
    const int arow = wm + (lane & 15);   // + mt_*16
    const int akhi = lane >> 4;          // 0 = k 0-3, 1 = k 4-7
    const int asw  = arow & 7;           // swizzle key (mt_*16 keeps row&7)
    const int bk   = lane & 3;
    const int bnf  = wnf + (lane >> 2);

    for (int kt = 0; kt < 32; kt++) {
        if (kt + 1 < 32) {
            int k0 = (kt + 1) << 5;
            int st = (kt + 1) & 1;
#pragma unroll
            for (int i = 0; i < 4; i++) {
                asm volatile("cp.async.cg.shared.global [%0], [%1], 16;"
                             :: "r"(smemu + 4u * (st * 4096 + aoff[i])),
                                "l"(Ag + agoff[i] + k0));
                asm volatile("cp.async.cg.shared.global [%0], [%1], 16;"
                             :: "r"(smemu + 4u * (st * 4352 + boff[i])),
                                "l"(Bg + bgoff[i] + (size_t)k0 * 2048));
            }
            asm volatile("cp.async.commit_group;" ::: "memory");
            asm volatile("cp.async.wait_group 1;" ::: "memory");
        } else {
            asm volatile("cp.async.wait_group 0;" ::: "memory");
        }
        __syncthreads();

        const int st = kt & 1;
        const uint32_t abase = smemu + 4u * (st * 4096);
        const uint32_t* Bu = (const uint32_t*)(smem + 8192 + st * 4352) + bk * 136 + bnf;

#pragma unroll
        for (int ks = 0; ks < 4; ks++) {
            uint32_t afr[4][4];
#pragma unroll
            for (int mti = 0; mti < 4; mti++) {
                uint32_t addr = abase + 4u * ((arow + mti * 16) * 32 +
                                              (((ks * 2 + akhi) ^ asw) << 2));
                asm volatile("ldmatrix.sync.aligned.m8n8.x4.shared.b16 {%0,%1,%2,%3}, [%4];"
                             : "=r"(afr[mti][0]), "=r"(afr[mti][1]),
                               "=r"(afr[mti][2]), "=r"(afr[mti][3]) : "r"(addr));
            }
            uint32_t bfr[4][2];
#pragma unroll
            for (int nt = 0; nt < 4; nt++) {
                const uint32_t* bp = Bu + (ks * 8) * 136 + nt * 8;
                bfr[nt][0] = bp[0];
                bfr[nt][1] = bp[4 * 136];
            }
#pragma unroll
            for (int mti = 0; mti < 4; mti++)
#pragma unroll
                for (int nt = 0; nt < 4; nt++) {
                    asm volatile("mma.sync.aligned.m16n8k8.row.col.f32.tf32.tf32.f32 "
                                 "{%0,%1,%2,%3}, {%4,%5,%6,%7}, {%8,%9}, {%0,%1,%2,%3};"
                                 : "+f"(acc[mti][nt][0]), "+f"(acc[mti][nt][1]),
                                   "+f"(acc[mti][nt][2]), "+f"(acc[mti][nt][3])
                                 : "r"(afr[mti][0]), "r"(afr[mti][1]),
                                   "r"(afr[mti][2]), "r"(afr[mti][3]),
                                   "r"(bfr[nt][0]),  "r"(bfr[nt][1]));
                }
        }
        __syncthreads();
    }

    // ------------- epilogue: relu, v store, s = sum_d q*relu(k) -------------
    // C fragment: thread owns cols {2*(lane&3), 2*(lane&3)+1} per n-tile,
    // i.e. an adjacent (k-channel, v-channel) pair for d = wnf/2 + nt*4 + lane&3.
    const int bidx = m0 >> 12;           // batch
    const int t0   = m0 & (TT - 1);
    const int bh   = bidx * TH + h;
    const int d0   = (wnf >> 1) + (lane & 3);
    float qv[4];
#pragma unroll
    for (int nt = 0; nt < 4; nt++) qv[nt] = Qk[h * 64 + d0 + nt * 4];

    float* Vb = g_V + ((size_t)bh * TT + t0) * 64;
    float* spart = smem;                 // reuse smem: [4 warps_n][128 rows]

#pragma unroll
    for (int mti = 0; mti < 4; mti++) {
#pragma unroll
        for (int half = 0; half < 2; half++) {
            float sp = 0.f;
            int row = wm + mti * 16 + (lane >> 2) + half * 8;
#pragma unroll
            for (int nt = 0; nt < 4; nt++) {
                float kk = fmaxf(acc[mti][nt][half * 2], 0.f);
                float vv = fmaxf(acc[mti][nt][half * 2 + 1], 0.f);
                sp = fmaf(qv[nt], kk, sp);
                Vb[(size_t)row * 64 + d0 + nt * 4] = vv;
            }
            sp += __shfl_xor_sync(0xffffffffu, sp, 1);
            sp += __shfl_xor_sync(0xffffffffu, sp, 2);
            if ((lane & 3) == 0) spart[(warp & 3) * 128 + row] = sp;
        }
    }
    __syncthreads();
    if (tid < 128) {
        float s = spart[tid] + spart[128 + tid] + spart[256 + tid] + spart[384 + tid];
        g_S[(size_t)bh * TT + t0 + tid] = s;
    }
}

// ---------------- kernel 2: online-softmax scan along T ---------------------
// One block per (b,h); 64 threads = d lanes. m/c are warp-uniform so the
// branch on a new running max never diverges (and is almost never taken).
__global__ void scan_kernel()
{
    const int bh = blockIdx.x;
    const int d  = threadIdx.x;
    const float* sp = g_S + (size_t)bh * TT;
    const float* vp = g_V + (size_t)bh * TT * 64 + d;
    float* hp       = g_Ha + (size_t)bh * TT * 64 + d;

    float m = __int_as_float(0xff800000);   // -inf
    float c = 0.f, a = 0.f;
#pragma unroll 8
    for (int t = 0; t < TT; t++) {
        float sv = __ldg(sp + t);
        float vv = __ldg(vp + (size_t)t * 64);
        if (sv > m) {                       // new running max (rare, uniform)
            float e = __expf(m - sv);
            c = fmaf(c, e, 1.0f);           // e_cur = exp(sv - sv) = 1
            a = fmaf(a, e, vv);
            m = sv;
        } else {
            float e = __expf(sv - m);
            c += e;
            a = fmaf(e, vv, a);
        }
        hp[(size_t)t * 64] = __fdividef(a, c);
    }
}

// ---------------- kernel 3: sum over heads ----------------------------------
__global__ void reduce_kernel(float* __restrict__ out)
{
    int idx = blockIdx.x * blockDim.x + threadIdx.x;   // b*T*D = 1048576
    if (idx >= TB * TT * TD) return;
    int b  = idx >> 18;                                // T*D = 262144 = 2^18
    int td = idx & 262143;
    const float* p = g_Ha + (size_t)b * TH * 262144 + td;
    float s = 0.f;
#pragma unroll
    for (int hh = 0; hh < TH; hh++) s += p[(size_t)hh * 262144];
    out[idx] = s;
}

// ---------------- launch ----------------------------------------------------
extern "C" void kernel_launch(void* const* d_in, const int* in_sizes, int n_in,
                              void* d_out, int out_size)
{
    const float* x = (const float*)d_in[0];   // inputs    [4,4096,1024]
    const float* w = (const float*)d_in[1];   // kv_kernel [1024,16,64,2]
    const float* q = (const float*)d_in[2];   // q_kernel  [16,64]
    float* out = (float*)d_out;               // [4,4096,64] f32

    cvt_tf32_kernel<<<4194304 / 256, 256>>>((const float4*)x, 4194304, 0);
    cvt_tf32_kernel<<<524288  / 256, 256>>>((const float4*)w, 524288, 1);

    cudaFuncSetAttribute(gemm_epilogue_kernel,
                         cudaFuncAttributeMaxDynamicSharedMemorySize, 67584);
    dim3 grid(16, 128);   // h fastest -> 16 head-blocks share each X tile via L2
    gemm_epilogue_kernel<<<grid, 256, 67584>>>(q);

    scan_kernel<<<64, 64>>>();
    reduce_kernel<<<4096, 256>>>(out);
}

// round 2
// speedup vs baseline: 2.6945x; 2.6945x over previous
#include <cuda_runtime.h>
#include <cstdint>

// Problem dims (fixed): B=4, T=4096, D_IN=1024, H=16, D=64
#define TB 4
#define TT 4096
#define TDIN 1024
#define TH 16
#define TD 64
#define NC 64     // chunks per (b,h)
#define CT 64     // timesteps per chunk

// ---------------- scratch (static device arrays; no runtime alloc) ----------
__device__ float g_Xc[16384ull * 1024];      // tf32-rounded X          (64 MB)
__device__ float g_Wc[1024ull * 2048];       // tf32-rounded W          ( 8 MB)
__device__ float g_V [64ull * 4096 * 64];    // v[b*16+h][t][d]         (64 MB)
__device__ float g_S [64ull * 4096];         // s[b*16+h][t]            ( 1 MB)
__device__ float g_Ha[64ull * 4096 * 64];    // (a/c)[b*16+h][t][d]     (64 MB)
__device__ float g_M [64];                   // max_t s per bh
__device__ float g_E [64 * NC];              // chunk e-sums -> excl prefix
__device__ float g_W [64ull * NC * 64];      // chunk e*v sums -> excl prefix

// ---------------- kernel 0: round inputs to tf32 (RNA) ----------------------
__global__ void cvt_tf32_kernel(const float4* __restrict__ in, int n4, int which)
{
    int i = blockIdx.x * blockDim.x + threadIdx.x;
    if (i >= n4) return;
    float4 v = in[i];
    uint32_t r;
    asm("cvt.rna.tf32.f32 %0, %1;" : "=r"(r) : "f"(v.x)); v.x = __uint_as_float(r);
    asm("cvt.rna.tf32.f32 %0, %1;" : "=r"(r) : "f"(v.y)); v.y = __uint_as_float(r);
    asm("cvt.rna.tf32.f32 %0, %1;" : "=r"(r) : "f"(v.z)); v.z = __uint_as_float(r);
    asm("cvt.rna.tf32.f32 %0, %1;" : "=r"(r) : "f"(v.w)); v.w = __uint_as_float(r);
    float4* out = which ? (float4*)g_Wc : (float4*)g_Xc;
    out[i] = v;
}

// ---------------- kernel 1: tf32 GEMM + relu + q-dot + v store --------------
__global__ __launch_bounds__(256, 2)
void gemm_epilogue_kernel(const float* __restrict__ Qk)
{
    extern __shared__ float smem[];
    const int h   = blockIdx.x;          // 0..15
    const int mt  = blockIdx.y;          // 0..127
    const int m0  = mt << 7;
    const int tid = threadIdx.x;
    const int lane = tid & 31, warp = tid >> 5;
    const int wm  = (warp >> 2) << 6;    // 0 / 64   (M offset)
    const int wnf = (warp & 3) << 5;     // 0/32/64/96 (N float offset)

    const float* Ag = g_Xc + (size_t)m0 * TDIN;
    const float* Bg = g_Wc + (h << 7);

    int aoff[4], boff[4], agoff[4], bgoff[4];
#pragma unroll
    for (int i = 0; i < 4; i++) {
        int id = tid + i * 256;
        int ar = id >> 3, ac4 = id & 7;
        aoff[i]  = ar * 32 + ((ac4 ^ (ar & 7)) << 2);
        agoff[i] = ar * TDIN + (ac4 << 2);
        int br = id >> 5, bc4 = id & 31;
        boff[i]  = 8192 + br * 136 + (bc4 << 2);
        bgoff[i] = br * 2048 + (bc4 << 2);
    }
    uint32_t smemu = (uint32_t)__cvta_generic_to_shared(smem);

#pragma unroll
    for (int i = 0; i < 4; i++) {
        asm volatile("cp.async.cg.shared.global [%0], [%1], 16;"
                     :: "r"(smemu + 4u * aoff[i]), "l"(Ag + agoff[i]));
        asm volatile("cp.async.cg.shared.global [%0], [%1], 16;"
                     :: "r"(smemu + 4u * boff[i]), "l"(Bg + bgoff[i]));
    }
    asm volatile("cp.async.commit_group;" ::: "memory");

    float acc[4][4][4];
#pragma unroll
    for (int i0 = 0; i0 < 4; i0++)
#pragma unroll
        for (int i1 = 0; i1 < 4; i1++)
#pragma unroll
            for (int i2 = 0; i2 < 4; i2++) acc[i0][i1][i2] = 0.f;

    const int arow = wm + (lane & 15);
    const int akhi = lane >> 4;
    const int asw  = arow & 7;
    const int bk   = lane & 3;
    const int bnf  = wnf + (lane >> 2);

    for (int kt = 0; kt < 32; kt++) {
        if (kt + 1 < 32) {
            int k0 = (kt + 1) << 5;
            int st = (kt + 1) & 1;
#pragma unroll
            for (int i = 0; i < 4; i++) {
                asm volatile("cp.async.cg.shared.global [%0], [%1], 16;"
                             :: "r"(smemu + 4u * (st * 4096 + aoff[i])),
                                "l"(Ag + agoff[i] + k0));
                asm volatile("cp.async.cg.shared.global [%0], [%1], 16;"
                             :: "r"(smemu + 4u * (st * 4352 + boff[i])),
                                "l"(Bg + bgoff[i] + (size_t)k0 * 2048));
            }
            asm volatile("cp.async.commit_group;" ::: "memory");
            asm volatile("cp.async.wait_group 1;" ::: "memory");
        } else {
            asm volatile("cp.async.wait_group 0;" ::: "memory");
        }
        __syncthreads();

        const int st = kt & 1;
        const uint32_t abase = smemu + 4u * (st * 4096);
        const uint32_t* Bu = (const uint32_t*)(smem + 8192 + st * 4352) + bk * 136 + bnf;

#pragma unroll
        for (int ks = 0; ks < 4; ks++) {
            uint32_t afr[4][4];
#pragma unroll
            for (int mti = 0; mti < 4; mti++) {
                uint32_t addr = abase + 4u * ((arow + mti * 16) * 32 +
                                              (((ks * 2 + akhi) ^ asw) << 2));
                asm volatile("ldmatrix.sync.aligned.m8n8.x4.shared.b16 {%0,%1,%2,%3}, [%4];"
                             : "=r"(afr[mti][0]), "=r"(afr[mti][1]),
                               "=r"(afr[mti][2]), "=r"(afr[mti][3]) : "r"(addr));
            }
            uint32_t bfr[4][2];
#pragma unroll
            for (int nt = 0; nt < 4; nt++) {
                const uint32_t* bp = Bu + (ks * 8) * 136 + nt * 8;
                bfr[nt][0] = bp[0];
                bfr[nt][1] = bp[4 * 136];
            }
#pragma unroll
            for (int mti = 0; mti < 4; mti++)
#pragma unroll
                for (int nt = 0; nt < 4; nt++) {
                    asm volatile("mma.sync.aligned.m16n8k8.row.col.f32.tf32.tf32.f32 "
                                 "{%0,%1,%2,%3}, {%4,%5,%6,%7}, {%8,%9}, {%0,%1,%2,%3};"
                                 : "+f"(acc[mti][nt][0]), "+f"(acc[mti][nt][1]),
                                   "+f"(acc[mti][nt][2]), "+f"(acc[mti][nt][3])
                                 : "r"(afr[mti][0]), "r"(afr[mti][1]),
                                   "r"(afr[mti][2]), "r"(afr[mti][3]),
                                   "r"(bfr[nt][0]),  "r"(bfr[nt][1]));
                }
        }
        __syncthreads();
    }

    const int bidx = m0 >> 12;
    const int t0   = m0 & (TT - 1);
    const int bh   = bidx * TH + h;
    const int d0   = (wnf >> 1) + (lane & 3);
    float qv[4];
#pragma unroll
    for (int nt = 0; nt < 4; nt++) qv[nt] = Qk[h * 64 + d0 + nt * 4];

    float* Vb = g_V + ((size_t)bh * TT + t0) * 64;
    float* spart = smem;

#pragma unroll
    for (int mti = 0; mti < 4; mti++) {
#pragma unroll
        for (int half = 0; half < 2; half++) {
            float sp = 0.f;
            int row = wm + mti * 16 + (lane >> 2) + half * 8;
#pragma unroll
            for (int nt = 0; nt < 4; nt++) {
                float kk = fmaxf(acc[mti][nt][half * 2], 0.f);
                float vv = fmaxf(acc[mti][nt][half * 2 + 1], 0.f);
                sp = fmaf(qv[nt], kk, sp);
                Vb[(size_t)row * 64 + d0 + nt * 4] = vv;
            }
            sp += __shfl_xor_sync(0xffffffffu, sp, 1);
            sp += __shfl_xor_sync(0xffffffffu, sp, 2);
            if ((lane & 3) == 0) spart[(warp & 3) * 128 + row] = sp;
        }
    }
    __syncthreads();
    if (tid < 128) {
        float s = spart[tid] + spart[128 + tid] + spart[256 + tid] + spart[384 + tid];
        g_S[(size_t)bh * TT + t0 + tid] = s;
    }
}

// ---------------- kernel 2a: per-(b,h) max of s -----------------------------
__global__ void max_kernel()
{
    const int bh = blockIdx.x, tid = threadIdx.x;   // 256 threads
    const float* sp = g_S + (size_t)bh * TT;
    float m = __int_as_float(0xff800000);
    for (int i = tid; i < TT; i += 256) m = fmaxf(m, sp[i]);
#pragma unroll
    for (int o = 16; o; o >>= 1) m = fmaxf(m, __shfl_xor_sync(0xffffffffu, m, o));
    __shared__ float sm[8];
    if ((tid & 31) == 0) sm[tid >> 5] = m;
    __syncthreads();
    if (tid < 8) {
        m = sm[tid];
#pragma unroll
        for (int o = 4; o; o >>= 1) m = fmaxf(m, __shfl_xor_sync(0xffu, m, o));
        if (tid == 0) g_M[bh] = m;
    }
}

// ---------------- kernel 2b: chunk partial sums E, W[d] ---------------------
__global__ void partial_kernel()
{
    const int ch = blockIdx.x, bh = blockIdx.y, tid = threadIdx.x;  // 64 thr
    __shared__ float es[CT];
    __shared__ float ws[2];
    const float M = g_M[bh];
    const float* sp = g_S + (size_t)bh * TT + ch * CT;
    float e = __expf(sp[tid] - M);
    es[tid] = e;
    float se = e;
#pragma unroll
    for (int o = 16; o; o >>= 1) se += __shfl_xor_sync(0xffffffffu, se, o);
    if ((tid & 31) == 0) ws[tid >> 5] = se;
    __syncthreads();
    if (tid == 0) g_E[bh * NC + ch] = ws[0] + ws[1];

    const float* vp = g_V + ((size_t)bh * TT + ch * CT) * TD + tid;
    float w = 0.f;
#pragma unroll
    for (int t = 0; t < CT; t++) w = fmaf(es[t], vp[(size_t)t * TD], w);
    g_W[((size_t)bh * NC + ch) * TD + tid] = w;
}

// ---------------- kernel 2c: exclusive scan of chunk aggregates -------------
__global__ void scanagg_kernel()
{
    const int bh = blockIdx.x, d = threadIdx.x;     // 64 threads
    float* wp = g_W + (size_t)bh * NC * TD + d;
    float aw = 0.f;
    for (int c = 0; c < NC; c++) {
        float t = wp[(size_t)c * TD];
        wp[(size_t)c * TD] = aw;
        aw += t;
    }
    if (d == 0) {
        float* ep = g_E + bh * NC;
        float ae = 0.f;
        for (int c = 0; c < NC; c++) { float t = ep[c]; ep[c] = ae; ae += t; }
    }
}

// ---------------- kernel 2d: apply prefix + local scan, write h=a/c ---------
__global__ void final_kernel()
{
    const int ch = blockIdx.x, bh = blockIdx.y, tid = threadIdx.x;  // 64 thr
    __shared__ float es[CT], rc[CT], wsum[2];
    const float M = g_M[bh];
    const float* sp = g_S + (size_t)bh * TT + ch * CT;
    float e = __expf(sp[tid] - M);
    // inclusive prefix of e across 64 threads
    float p = e;
#pragma unroll
    for (int o = 1; o < 32; o <<= 1) {
        float t = __shfl_up_sync(0xffffffffu, p, o);
        if ((tid & 31) >= o) p += t;
    }
    if ((tid & 31) == 31) wsum[tid >> 5] = p;
    es[tid] = e;
    __syncthreads();
    const float c0 = g_E[bh * NC + ch];                 // exclusive prefix
    float cin = c0 + p + ((tid >= 32) ? wsum[0] : 0.f); // inclusive c_t
    rc[tid] = 1.0f / cin;
    __syncthreads();

    float a = g_W[((size_t)bh * NC + ch) * TD + tid];   // exclusive prefix a_d
    const float* vp = g_V + ((size_t)bh * TT + ch * CT) * TD + tid;
    float* hp       = g_Ha + ((size_t)bh * TT + ch * CT) * TD + tid;
#pragma unroll
    for (int t = 0; t < CT; t++) {
        a = fmaf(es[t], vp[(size_t)t * TD], a);
        hp[(size_t)t * TD] = a * rc[t];
    }
}

// ---------------- kernel 3: sum over heads ----------------------------------
__global__ void reduce_kernel(float* __restrict__ out)
{
    int idx = blockIdx.x * blockDim.x + threadIdx.x;   // b*T*D = 1048576
    if (idx >= TB * TT * TD) return;
    int b  = idx >> 18;
    int td = idx & 262143;
    const float* p = g_Ha + (size_t)b * TH * 262144 + td;
    float s = 0.f;
#pragma unroll
    for (int hh = 0; hh < TH; hh++) s += p[(size_t)hh * 262144];
    out[idx] = s;
}

// ---------------- launch ----------------------------------------------------
extern "C" void kernel_launch(void* const* d_in, const int* in_sizes, int n_in,
                              void* d_out, int out_size)
{
    const float* x = (const float*)d_in[0];
    const float* w = (const float*)d_in[1];
    const float* q = (const float*)d_in[2];
    float* out = (float*)d_out;

    cvt_tf32_kernel<<<4194304 / 256, 256>>>((const float4*)x, 4194304, 0);
    cvt_tf32_kernel<<<524288  / 256, 256>>>((const float4*)w, 524288, 1);

    cudaFuncSetAttribute(gemm_epilogue_kernel,
                         cudaFuncAttributeMaxDynamicSharedMemorySize, 67584);
    dim3 grid(16, 128);
    gemm_epilogue_kernel<<<grid, 256, 67584>>>(q);

    max_kernel<<<64, 256>>>();
    partial_kernel<<<dim3(NC, 64), CT>>>();
    scanagg_kernel<<<64, TD>>>();
    final_kernel<<<dim3(NC, 64), CT>>>();
    reduce_kernel<<<4096, 256>>>(out);
}